// round 4
// baseline (speedup 1.0000x reference)
#include <cuda_runtime.h>

#define NF      26
#define VOCAB   100000
#define EMBED   16
#define BATCH   16384
#define KDIM    16
#define NTOT    (NF * EMBED)   // 416
#define VSTRIDE 20             // padded row stride (floats) -> conflict-free float4 LDS
#define THREADS 256

extern __shared__ float smem[];

__global__ __launch_bounds__(THREADS)
void fm_kernel(const int* __restrict__ X,
               const float* __restrict__ tables,
               const float* __restrict__ W,
               const float* __restrict__ bptr,
               const float* __restrict__ v,
               float* __restrict__ out)
{
    float* v_sh  = smem;                     // [NTOT][VSTRIDE]
    float* v2_sh = smem + NTOT * VSTRIDE;    // [NTOT][VSTRIDE]

    const int tid = threadIdx.x;

    // Stage v and v^2 into padded shared memory.
    for (int i = tid; i < NTOT * KDIM; i += THREADS) {
        int n = i >> 4;
        int k = i & 15;
        float val = v[i];
        v_sh [n * VSTRIDE + k] = val;
        v2_sh[n * VSTRIDE + k] = val * val;
    }

    const int lane = tid & 31;
    const int j    = lane & 15;              // embedding component owned by this lane
    const int warp = tid >> 5;
    const int row  = blockIdx.x * 16 + warp * 2 + (lane >> 4);

    // W components this lane needs, one per field (register array, fully unrolled).
    float Wreg[NF];
#pragma unroll
    for (int f = 0; f < NF; f++) Wreg[f] = __ldg(&W[f * EMBED + j]);
    const float bval = __ldg(bptr);

    __syncthreads();

    float xv[KDIM], ss[KDIM];
#pragma unroll
    for (int k = 0; k < KDIM; k++) { xv[k] = 0.f; ss[k] = 0.f; }
    float lin = 0.f;

    const int* xrow = X + row * NF;

#pragma unroll
    for (int f = 0; f < NF; f++) {
        int idx = __ldg(&xrow[f]);
        const float* e_ptr = tables + ((long long)f * VOCAB + idx) * EMBED;
        float e  = __ldg(&e_ptr[j]);         // half-warp covers the 64B embedding line
        lin = fmaf(e, Wreg[f], lin);
        float e2 = e * e;

        const float4* vr  = (const float4*)(v_sh  + (f * EMBED + j) * VSTRIDE);
        const float4* v2r = (const float4*)(v2_sh + (f * EMBED + j) * VSTRIDE);
#pragma unroll
        for (int kq = 0; kq < 4; kq++) {
            float4 a  = vr[kq];
            float4 b2 = v2r[kq];
            xv[kq * 4 + 0] = fmaf(e, a.x, xv[kq * 4 + 0]);
            xv[kq * 4 + 1] = fmaf(e, a.y, xv[kq * 4 + 1]);
            xv[kq * 4 + 2] = fmaf(e, a.z, xv[kq * 4 + 2]);
            xv[kq * 4 + 3] = fmaf(e, a.w, xv[kq * 4 + 3]);
            ss[kq * 4 + 0] = fmaf(e2, b2.x, ss[kq * 4 + 0]);
            ss[kq * 4 + 1] = fmaf(e2, b2.y, ss[kq * 4 + 1]);
            ss[kq * 4 + 2] = fmaf(e2, b2.z, ss[kq * 4 + 2]);
            ss[kq * 4 + 3] = fmaf(e2, b2.w, ss[kq * 4 + 3]);
        }
    }

    // Reduce over j within each half-warp (width-16 butterfly; offsets <=8 stay in-half).
#pragma unroll
    for (int off = 8; off >= 1; off >>= 1) {
#pragma unroll
        for (int k = 0; k < KDIM; k++) {
            xv[k] += __shfl_xor_sync(0xffffffffu, xv[k], off);
            ss[k] += __shfl_xor_sync(0xffffffffu, ss[k], off);
        }
        lin += __shfl_xor_sync(0xffffffffu, lin, off);
    }

    float inter = 0.f;
#pragma unroll
    for (int k = 0; k < KDIM; k++) inter += xv[k] * xv[k] - ss[k];

    float z = lin + bval + 0.5f * inter;

    if (j == 0) out[row] = 1.f / (1.f + __expf(-z));
}

extern "C" void kernel_launch(void* const* d_in, const int* in_sizes, int n_in,
                              void* d_out, int out_size)
{
    const int*   X      = (const int*)d_in[0];
    const float* tables = (const float*)d_in[1];
    const float* W      = (const float*)d_in[2];
    const float* b      = (const float*)d_in[3];
    const float* v      = (const float*)d_in[4];
    float*       out    = (float*)d_out;

    const size_t shmem = (size_t)2 * NTOT * VSTRIDE * sizeof(float);  // 66560 B
    cudaFuncSetAttribute(fm_kernel, cudaFuncAttributeMaxDynamicSharedMemorySize,
                         (int)shmem);

    // 16 rows per block (8 warps x 2 rows), 1024 blocks covers BATCH=16384.
    fm_kernel<<<BATCH / 16, THREADS, shmem>>>(X, tables, W, b, v, out);
}

// round 5
// speedup vs baseline: 1.0057x; 1.0057x over previous
#include <cuda_runtime.h>

#define NF      26
#define VOCAB   100000
#define EMBED   16
#define BATCH   16384
#define KDIM    16
#define NTOT    (NF * EMBED)   // 416
#define VSTRIDE 20             // padded row stride (floats) -> conflict-free float4 LDS
#define THREADS 256

extern __shared__ float smem[];

__global__ __launch_bounds__(THREADS)
void fm_kernel(const int* __restrict__ X,
               const float* __restrict__ tables,
               const float* __restrict__ W,
               const float* __restrict__ bptr,
               const float* __restrict__ v,
               float* __restrict__ out)
{
    float* v_sh  = smem;                     // [NTOT][VSTRIDE]
    float* s2_sh = smem + NTOT * VSTRIDE;    // [NTOT]  rowwise sum of v^2

    const int tid = threadIdx.x;

    // Stage v into padded shared memory and compute s2[n] = sum_k v[n][k]^2.
    for (int n = tid; n < NTOT; n += THREADS) {
        const float4* vr = (const float4*)(v + n * KDIM);
        float s2 = 0.f;
#pragma unroll
        for (int q = 0; q < 4; q++) {
            float4 a = vr[q];
            v_sh[n * VSTRIDE + q * 4 + 0] = a.x;
            v_sh[n * VSTRIDE + q * 4 + 1] = a.y;
            v_sh[n * VSTRIDE + q * 4 + 2] = a.z;
            v_sh[n * VSTRIDE + q * 4 + 3] = a.w;
            s2 += a.x * a.x + a.y * a.y + a.z * a.z + a.w * a.w;
        }
        s2_sh[n] = s2;
    }

    const int lane = tid & 31;
    const int j    = lane & 15;              // embedding component owned by this lane
    const int warp = tid >> 5;
    const int row  = blockIdx.x * 16 + warp * 2 + (lane >> 4);

    // Per-lane constants held in registers: W and s2 for this lane's components.
    float Wreg[NF];
#pragma unroll
    for (int f = 0; f < NF; f++) Wreg[f] = __ldg(&W[f * EMBED + j]);
    const float bval = __ldg(bptr);

    __syncthreads();

    float Sreg[NF];
#pragma unroll
    for (int f = 0; f < NF; f++) Sreg[f] = s2_sh[f * EMBED + j];

    float xv[KDIM];
#pragma unroll
    for (int k = 0; k < KDIM; k++) xv[k] = 0.f;
    float lin  = 0.f;
    float ssum = 0.f;                        // sum over n of e^2 * s2[n]

    const int* xrow = X + row * NF;

#pragma unroll
    for (int f = 0; f < NF; f++) {
        int idx = __ldg(&xrow[f]);
        const float* e_ptr = tables + ((long long)f * VOCAB + idx) * EMBED;
        float e = __ldg(&e_ptr[j]);          // half-warp covers the 64B embedding line
        lin  = fmaf(e, Wreg[f], lin);
        ssum = fmaf(e * e, Sreg[f], ssum);

        const float4* vr = (const float4*)(v_sh + (f * EMBED + j) * VSTRIDE);
#pragma unroll
        for (int kq = 0; kq < 4; kq++) {
            float4 a = vr[kq];
            xv[kq * 4 + 0] = fmaf(e, a.x, xv[kq * 4 + 0]);
            xv[kq * 4 + 1] = fmaf(e, a.y, xv[kq * 4 + 1]);
            xv[kq * 4 + 2] = fmaf(e, a.z, xv[kq * 4 + 2]);
            xv[kq * 4 + 3] = fmaf(e, a.w, xv[kq * 4 + 3]);
        }
    }

    // Reduce over j within each half-warp (width-16 butterfly; offsets <=8 stay in-half).
#pragma unroll
    for (int off = 8; off >= 1; off >>= 1) {
#pragma unroll
        for (int k = 0; k < KDIM; k++)
            xv[k] += __shfl_xor_sync(0xffffffffu, xv[k], off);
        lin  += __shfl_xor_sync(0xffffffffu, lin,  off);
        ssum += __shfl_xor_sync(0xffffffffu, ssum, off);
    }

    float inter = -ssum;
#pragma unroll
    for (int k = 0; k < KDIM; k++) inter = fmaf(xv[k], xv[k], inter);

    float z = lin + bval + 0.5f * inter;

    if (j == 0) out[row] = 1.f / (1.f + __expf(-z));
}

extern "C" void kernel_launch(void* const* d_in, const int* in_sizes, int n_in,
                              void* d_out, int out_size)
{
    const int*   X      = (const int*)d_in[0];
    const float* tables = (const float*)d_in[1];
    const float* W      = (const float*)d_in[2];
    const float* b      = (const float*)d_in[3];
    const float* v      = (const float*)d_in[4];
    float*       out    = (float*)d_out;

    const size_t shmem = (size_t)(NTOT * VSTRIDE + NTOT) * sizeof(float); // 34944 B
    cudaFuncSetAttribute(fm_kernel, cudaFuncAttributeMaxDynamicSharedMemorySize,
                         (int)shmem);

    // 16 rows per block (8 warps x 2 rows), 1024 blocks covers BATCH=16384.
    fm_kernel<<<BATCH / 16, THREADS, shmem>>>(X, tables, W, b, v, out);
}

// round 7
// speedup vs baseline: 1.4474x; 1.4393x over previous
#include <cuda_runtime.h>

#define NF      26
#define VOCAB   100000
#define EMBED   16
#define BATCH   16384
#define KDIM    16
#define NTOT    (NF * EMBED)   // 416
#define VSTRIDE 20             // [v0..v15, W, s2, pad, pad] -> conflict-free float4 LDS
#define THREADS 256

extern __shared__ float smem[];

__global__ __launch_bounds__(THREADS)
void fm_kernel(const int* __restrict__ X,
               const float* __restrict__ tables,
               const float* __restrict__ W,
               const float* __restrict__ bptr,
               const float* __restrict__ v,
               float* __restrict__ out)
{
    float* v_sh = smem;                      // [NTOT][VSTRIDE]

    const int tid = threadIdx.x;

    // Stage augmented tile: row n = [v[n][0..15], W[n], s2[n], 0, 0]
    for (int n = tid; n < NTOT; n += THREADS) {
        const float4* vr = (const float4*)(v + n * KDIM);
        float s2 = 0.f;
#pragma unroll
        for (int q = 0; q < 4; q++) {
            float4 a = vr[q];
            ((float4*)(v_sh + n * VSTRIDE))[q] = a;
            s2 += a.x * a.x + a.y * a.y + a.z * a.z + a.w * a.w;
        }
        v_sh[n * VSTRIDE + 16] = __ldg(&W[n]);
        v_sh[n * VSTRIDE + 17] = s2;
        v_sh[n * VSTRIDE + 18] = 0.f;
        v_sh[n * VSTRIDE + 19] = 0.f;
    }

    const int lane = tid & 31;
    const int j    = lane & 15;              // embedding component owned by this lane
    const int warp = tid >> 5;
    const int row  = blockIdx.x * 16 + warp * 2 + (lane >> 4);
    const float bval = __ldg(bptr);

    __syncthreads();

    float xv[KDIM];
#pragma unroll
    for (int k = 0; k < KDIM; k++) xv[k] = 0.f;
    float lin  = 0.f;                        // sum_n e_n * W_n
    float ssum = 0.f;                        // sum_n e_n^2 * s2_n

    const int* xrow = X + row * NF;

#pragma unroll
    for (int f = 0; f < NF; f++) {
        int idx = __ldg(&xrow[f]);
        const float* e_ptr = tables + ((long long)f * VOCAB + idx) * EMBED;
        float e = __ldg(&e_ptr[j]);          // half-warp covers the 64B embedding line

        const float4* vr = (const float4*)(v_sh + (f * EMBED + j) * VSTRIDE);
#pragma unroll
        for (int kq = 0; kq < 4; kq++) {
            float4 a = vr[kq];
            xv[kq * 4 + 0] = fmaf(e, a.x, xv[kq * 4 + 0]);
            xv[kq * 4 + 1] = fmaf(e, a.y, xv[kq * 4 + 1]);
            xv[kq * 4 + 2] = fmaf(e, a.z, xv[kq * 4 + 2]);
            xv[kq * 4 + 3] = fmaf(e, a.w, xv[kq * 4 + 3]);
        }
        float4 ws = vr[4];                   // .x = W[n], .y = s2[n]
        lin  = fmaf(e,     ws.x, lin);
        ssum = fmaf(e * e, ws.y, ssum);
    }

    // Reduce over j within each half-warp (width-16 butterfly; offsets <=8 stay in-half).
#pragma unroll
    for (int off = 8; off >= 1; off >>= 1) {
#pragma unroll
        for (int k = 0; k < KDIM; k++)
            xv[k] += __shfl_xor_sync(0xffffffffu, xv[k], off);
        lin  += __shfl_xor_sync(0xffffffffu, lin,  off);
        ssum += __shfl_xor_sync(0xffffffffu, ssum, off);
    }

    float inter = -ssum;
#pragma unroll
    for (int k = 0; k < KDIM; k++) inter = fmaf(xv[k], xv[k], inter);

    float z = lin + bval + 0.5f * inter;

    if (j == 0) out[row] = 1.f / (1.f + __expf(-z));
}

extern "C" void kernel_launch(void* const* d_in, const int* in_sizes, int n_in,
                              void* d_out, int out_size)
{
    const int*   X      = (const int*)d_in[0];
    const float* tables = (const float*)d_in[1];
    const float* W      = (const float*)d_in[2];
    const float* b      = (const float*)d_in[3];
    const float* v      = (const float*)d_in[4];
    float*       out    = (float*)d_out;

    const size_t shmem = (size_t)NTOT * VSTRIDE * sizeof(float);   // 33280 B
    cudaFuncSetAttribute(fm_kernel, cudaFuncAttributeMaxDynamicSharedMemorySize,
                         (int)shmem);

    // 16 rows per block (8 warps x 2 rows), 1024 blocks covers BATCH=16384.
    fm_kernel<<<BATCH / 16, THREADS, shmem>>>(X, tables, W, b, v, out);
}

// round 8
// speedup vs baseline: 1.7019x; 1.1758x over previous
#include <cuda_runtime.h>

#define NF      26
#define VOCAB   100000
#define EMBED   16
#define BATCH   16384
#define KDIM    16
#define NTOT    (NF * EMBED)   // 416
#define VSTRIDE 20             // [v0..v15, W, s2, pad, pad] -> conflict-free float4 LDS
#define THREADS 128

extern __shared__ float smem[];

__global__ __launch_bounds__(THREADS)
void fm_kernel(const int* __restrict__ X,
               const float* __restrict__ tables,
               const float* __restrict__ W,
               const float* __restrict__ bptr,
               const float* __restrict__ v,
               float* __restrict__ out)
{
    float* v_sh = smem;                      // [NTOT][VSTRIDE]

    const int tid = threadIdx.x;

    // Stage augmented tile: row n = [v[n][0..15], W[n], s2[n], 0, 0]
    for (int n = tid; n < NTOT; n += THREADS) {
        const float4* vr = (const float4*)(v + n * KDIM);
        float s2 = 0.f;
#pragma unroll
        for (int q = 0; q < 4; q++) {
            float4 a = vr[q];
            ((float4*)(v_sh + n * VSTRIDE))[q] = a;
            s2 += a.x * a.x + a.y * a.y + a.z * a.z + a.w * a.w;
        }
        v_sh[n * VSTRIDE + 16] = __ldg(&W[n]);
        v_sh[n * VSTRIDE + 17] = s2;
        v_sh[n * VSTRIDE + 18] = 0.f;
        v_sh[n * VSTRIDE + 19] = 0.f;
    }

    const int lane = tid & 31;
    const int j    = lane & 15;              // embedding component owned by this lane
    const int warp = tid >> 5;
    // Warp covers 4 rows: lanes 0-15 -> rows r0,r1 ; lanes 16-31 -> rows r2,r3.
    const int row0 = blockIdx.x * 16 + warp * 4 + (lane >> 4) * 2;
    const int row1 = row0 + 1;
    const float bval = __ldg(bptr);

    __syncthreads();

    float xv0[KDIM], xv1[KDIM];
#pragma unroll
    for (int k = 0; k < KDIM; k++) { xv0[k] = 0.f; xv1[k] = 0.f; }
    float lin0 = 0.f, lin1 = 0.f;            // sum_n e_n * W_n
    float ss0  = 0.f, ss1  = 0.f;            // sum_n e_n^2 * s2_n

    const int* xrow0 = X + row0 * NF;
    const int* xrow1 = X + row1 * NF;

#pragma unroll
    for (int f = 0; f < NF; f++) {
        int idx0 = __ldg(&xrow0[f]);         // uniform across half-warp -> broadcast
        int idx1 = __ldg(&xrow1[f]);
        const float* base = tables + (long long)f * VOCAB * EMBED;
        float e0 = __ldg(base + (long long)idx0 * EMBED + j);  // half-warp covers 64B line
        float e1 = __ldg(base + (long long)idx1 * EMBED + j);

        const float4* vr = (const float4*)(v_sh + (f * EMBED + j) * VSTRIDE);
#pragma unroll
        for (int kq = 0; kq < 4; kq++) {
            float4 a = vr[kq];
            xv0[kq * 4 + 0] = fmaf(e0, a.x, xv0[kq * 4 + 0]);
            xv0[kq * 4 + 1] = fmaf(e0, a.y, xv0[kq * 4 + 1]);
            xv0[kq * 4 + 2] = fmaf(e0, a.z, xv0[kq * 4 + 2]);
            xv0[kq * 4 + 3] = fmaf(e0, a.w, xv0[kq * 4 + 3]);
            xv1[kq * 4 + 0] = fmaf(e1, a.x, xv1[kq * 4 + 0]);
            xv1[kq * 4 + 1] = fmaf(e1, a.y, xv1[kq * 4 + 1]);
            xv1[kq * 4 + 2] = fmaf(e1, a.z, xv1[kq * 4 + 2]);
            xv1[kq * 4 + 3] = fmaf(e1, a.w, xv1[kq * 4 + 3]);
        }
        float4 ws = vr[4];                   // .x = W[n], .y = s2[n]
        lin0 = fmaf(e0,      ws.x, lin0);
        lin1 = fmaf(e1,      ws.x, lin1);
        ss0  = fmaf(e0 * e0, ws.y, ss0);
        ss1  = fmaf(e1 * e1, ws.y, ss1);
    }

    // Reduce over j within each half-warp (XOR offsets <=8 stay inside the half).
#pragma unroll
    for (int off = 8; off >= 1; off >>= 1) {
#pragma unroll
        for (int k = 0; k < KDIM; k++) {
            xv0[k] += __shfl_xor_sync(0xffffffffu, xv0[k], off);
            xv1[k] += __shfl_xor_sync(0xffffffffu, xv1[k], off);
        }
        lin0 += __shfl_xor_sync(0xffffffffu, lin0, off);
        lin1 += __shfl_xor_sync(0xffffffffu, lin1, off);
        ss0  += __shfl_xor_sync(0xffffffffu, ss0,  off);
        ss1  += __shfl_xor_sync(0xffffffffu, ss1,  off);
    }

    float i0 = -ss0, i1 = -ss1;
#pragma unroll
    for (int k = 0; k < KDIM; k++) {
        i0 = fmaf(xv0[k], xv0[k], i0);
        i1 = fmaf(xv1[k], xv1[k], i1);
    }

    if (j == 0) {
        float z0 = lin0 + bval + 0.5f * i0;
        float z1 = lin1 + bval + 0.5f * i1;
        out[row0] = 1.f / (1.f + __expf(-z0));
        out[row1] = 1.f / (1.f + __expf(-z1));
    }
}

extern "C" void kernel_launch(void* const* d_in, const int* in_sizes, int n_in,
                              void* d_out, int out_size)
{
    const int*   X      = (const int*)d_in[0];
    const float* tables = (const float*)d_in[1];
    const float* W      = (const float*)d_in[2];
    const float* b      = (const float*)d_in[3];
    const float* v      = (const float*)d_in[4];
    float*       out    = (float*)d_out;

    const size_t shmem = (size_t)NTOT * VSTRIDE * sizeof(float);   // 33280 B
    cudaFuncSetAttribute(fm_kernel, cudaFuncAttributeMaxDynamicSharedMemorySize,
                         (int)shmem);

    // 16 rows per block (4 warps x 4 rows), 1024 blocks covers BATCH=16384.
    fm_kernel<<<BATCH / 16, THREADS, shmem>>>(X, tables, W, b, v, out);
}